// round 15
// baseline (speedup 1.0000x reference)
#include <cuda_runtime.h>
#include <cuda_fp16.h>
#include <math_constants.h>
#include <cstdint>

static constexpr int B  = 4;
static constexpr int S  = 2048;
static constexpr int D  = 512;
static constexpr int H  = 8;
static constexpr int DK = 64;
static constexpr int BH = B * H;            // 32
static constexpr int NCHUNK = 32;           // 2048 / 64
static constexpr float SCALE = 0.125f;      // DK^-0.5

// ---- scratch (device globals) ----
__device__ half g_Zqh[B * S * D],  g_Zql[B * S * D];
__device__ half g_Zkh[B * S * D],  g_Zkl[B * S * D];
__device__ half g_WqTh[3 * D * D], g_WqTl[3 * D * D];
__device__ half g_WoTh[D * D],     g_WoTl[D * D];
__device__ half g_Qh[BH * S * DK], g_Ql[BH * S * DK];
__device__ half g_Kh[BH * S * DK], g_Kl[BH * S * DK];
__device__ half g_Vth[BH * DK * S], g_Vtl[BH * DK * S];
__device__ half g_Ch[B * S * D],   g_Cl[B * S * D];
// e = exp(s - m_chunk) per element (fp32), + per-(row,chunk) stats
__device__ float g_E[(size_t)BH * S * S];                // 512 MB
__device__ float g_Mc[BH * S * NCHUNK];                  // 8 MB  [bh][q][kc]
__device__ float g_CF[BH * S * NCHUNK];                  // 8 MB  [bh][q][kc]
__device__ float g_M[BH * S];
__device__ float g_Li[BH * S];

// ============================================================
// helpers
// ============================================================
__device__ __forceinline__ void mma16(float* d, const uint32_t* a,
                                      uint32_t b0, uint32_t b1) {
    asm("mma.sync.aligned.m16n8k16.row.col.f32.f16.f16.f32 "
        "{%0,%1,%2,%3}, {%4,%5,%6,%7}, {%8,%9}, {%0,%1,%2,%3};"
        : "+f"(d[0]), "+f"(d[1]), "+f"(d[2]), "+f"(d[3])
        : "r"(a[0]), "r"(a[1]), "r"(a[2]), "r"(a[3]), "r"(b0), "r"(b1));
}
__device__ __forceinline__ void split2(float x, float y, uint32_t& hi, uint32_t& lo) {
    half2 h = __floats2half2_rn(x, y);
    half2 l = __floats2half2_rn(x - __low2float(h), y - __high2float(h));
    hi = *reinterpret_cast<uint32_t*>(&h);
    lo = *reinterpret_cast<uint32_t*>(&l);
}

// scatter one uint4 (8 halves: row n, cols k8..k8+7) into the permuted
// B-fragment layout: word = ((g*33 + (n&7)*4 + p)<<2) + j + lo_off
__device__ __forceinline__ void scat_b(uint32_t* Fw, int n, int k8, uint4 v, int lo_off) {
    const int g    = ((n >> 3) << 2) + (k8 >> 4);
    const int j    = (k8 >> 3) & 1;
    const int base = ((g * 33 + ((n & 7) << 2)) << 2) + j + lo_off;
    Fw[base + 0]  = v.x;
    Fw[base + 4]  = v.y;
    Fw[base + 8]  = v.z;
    Fw[base + 12] = v.w;
}

// ============================================================
// prep kernels
// ============================================================
__global__ __launch_bounds__(256) void split_kernel(
    const float4* __restrict__ src, uint2* __restrict__ dh,
    uint2* __restrict__ dl, int n4)
{
    const int i = blockIdx.x * 256 + threadIdx.x;
    if (i >= n4) return;
    float4 v = src[i];
    uint32_t h0, l0, h1, l1;
    split2(v.x, v.y, h0, l0);
    split2(v.z, v.w, h1, l1);
    uint2 ho = {h0, h1}, lo = {l0, l1};
    dh[i] = ho; dl[i] = lo;
}

__global__ __launch_bounds__(256) void tsplit_kernel(
    const float* __restrict__ src, half* __restrict__ dh,
    half* __restrict__ dl, int K, int N)
{
    const int idx = blockIdx.x * 256 + threadIdx.x;
    if (idx >= (K >> 3) * N) return;
    const int n  = idx % N;
    const int k8 = (idx / N) << 3;
    uint32_t h[4], l[4];
    #pragma unroll
    for (int p = 0; p < 4; p++) {
        float a = src[(size_t)(k8 + 2 * p) * N + n];
        float b = src[(size_t)(k8 + 2 * p + 1) * N + n];
        split2(a, b, h[p], l[p]);
    }
    uint4 hv = {h[0], h[1], h[2], h[3]};
    uint4 lv = {l[0], l[1], l[2], l[3]};
    *(uint4*)(dh + (size_t)n * K + k8) = hv;
    *(uint4*)(dl + (size_t)n * K + k8) = lv;
}

// CF[bh][q][kc] = exp(Mc - M) * Li
__global__ __launch_bounds__(256) void cf_kernel()
{
    const int idx = blockIdx.x * 256 + threadIdx.x;   // < BH*S*32
    const int row = idx >> 5;                          // bh*S + q
    g_CF[idx] = __expf(g_Mc[idx] - g_M[row]) * g_Li[row];
}

// ============================================================
// QKV projection: [8192x512]@[512x1536] -> split Q,K,V^T
// ============================================================
__global__ __launch_bounds__(128) void qkv_mma_kernel()
{
    __shared__ __align__(16) half Ast[2][64 * 72];
    __shared__ uint4 FragB[8 * 4 * 33];
    uint32_t* Fw = (uint32_t*)FragB;

    const int t = threadIdx.x, w = t >> 5, lane = t & 31;
    const int r = lane >> 2, c = lane & 3;
    const int m0 = blockIdx.x * 64;
    const int n0 = blockIdx.y * 64;
    const int part = n0 >> 9;
    const half* Ah_g = (part == 0) ? g_Zqh : g_Zkh;
    const half* Al_g = (part == 0) ? g_Zql : g_Zkl;
    const int dcol0 = n0 - (part << 9);

    float acc[8][4] = {};

    for (int kt = 0; kt < 512; kt += 64) {
        __syncthreads();
        #pragma unroll
        for (int i = 0; i < 4; i++) {
            int idx = t + i * 128;
            int row = idx >> 3, k8 = (idx & 7) << 3;
            *(uint4*)&Ast[0][row * 72 + k8] =
                *(const uint4*)(Ah_g + (size_t)(m0 + row) * 512 + kt + k8);
            *(uint4*)&Ast[1][row * 72 + k8] =
                *(const uint4*)(Al_g + (size_t)(m0 + row) * 512 + kt + k8);
        }
        #pragma unroll
        for (int i = 0; i < 4; i++) {
            int idx = t + i * 128;
            int n = idx >> 3, k8 = (idx & 7) << 3;
            uint4 vh = *(const uint4*)(g_WqTh + (size_t)(n0 + n) * 512 + kt + k8);
            uint4 vl = *(const uint4*)(g_WqTl + (size_t)(n0 + n) * 512 + kt + k8);
            scat_b(Fw, n, k8, vh, 0);
            scat_b(Fw, n, k8, vl, 2);
        }
        __syncthreads();

        #pragma unroll
        for (int ks = 0; ks < 4; ks++) {
            uint32_t ahi[4], alo[4];
            #pragma unroll
            for (int i = 0; i < 4; i++) {
                const int row = 16 * w + r + ((i & 1) << 3);
                const int col = ks * 16 + 2 * c + ((i >> 1) << 3);
                ahi[i] = *(const uint32_t*)&Ast[0][row * 72 + col];
                alo[i] = *(const uint32_t*)&Ast[1][row * 72 + col];
            }
            #pragma unroll
            for (int nt = 0; nt < 8; nt++) {
                uint4 bq = FragB[(nt * 4 + ks) * 33 + lane];
                mma16(acc[nt], ahi, bq.x, bq.y);
                mma16(acc[nt], ahi, bq.z, bq.w);
                mma16(acc[nt], alo, bq.x, bq.y);
            }
        }
    }

    const int mA = m0 + 16 * w + r, mB = mA + 8;
    #pragma unroll
    for (int nt = 0; nt < 8; nt++) {
        const int d = dcol0 + nt * 8 + 2 * c;
        const int hh = d >> 6, dk = d & 63;
        #pragma unroll
        for (int hm = 0; hm < 2; hm++) {
            const int m = hm ? mB : mA;
            const int bb = m >> 11, ss = m & 2047;
            uint32_t hi, lo;
            split2(acc[nt][2 * hm], acc[nt][2 * hm + 1], hi, lo);
            if (part == 2) {
                half2 h2 = *reinterpret_cast<half2*>(&hi);
                half2 l2 = *reinterpret_cast<half2*>(&lo);
                const size_t vb = ((size_t)(bb * H + hh) * DK + dk) * S + ss;
                g_Vth[vb]     = __low2half(h2);
                g_Vth[vb + S] = __high2half(h2);
                g_Vtl[vb]     = __low2half(l2);
                g_Vtl[vb + S] = __high2half(l2);
            } else {
                const size_t qb = ((size_t)(bb * H + hh) * S + ss) * DK + dk;
                half* dsth = (part == 0) ? g_Qh : g_Kh;
                half* dstl = (part == 0) ? g_Ql : g_Kl;
                *(uint32_t*)(dsth + qb) = hi;
                *(uint32_t*)(dstl + qb) = lo;
            }
        }
    }
}

// ============================================================
// scores: QK^T*scale + mask -> e = exp(s - m_chunk) stored to g_E,
// m_chunk to g_Mc, final m / 1/l to g_M / g_Li.
// 256 thr, q-strip 128, k chunks 64, double-buffered FragB.
// ============================================================
__global__ __launch_bounds__(256) void scores_mma_kernel(const float* __restrict__ mask)
{
    __shared__ __align__(16) char sraw[2][16896];      // double FragB; Q-stage spans both

    const int t = threadIdx.x, w = t >> 5, lane = t & 31;
    const int r = lane >> 2, c = lane & 3;
    const int bh = blockIdx.y, q0 = blockIdx.x * 128;
    const half* Qhb = g_Qh + ((size_t)bh * S + q0) * DK;
    const half* Qlb = g_Ql + ((size_t)bh * S + q0) * DK;
    const half* Khb = g_Kh + (size_t)bh * S * DK;
    const half* Klb = g_Kl + (size_t)bh * S * DK;
    float* Ep = g_E + (size_t)bh * S * S;

    // ---- stage Q (128x64, hi then lo) and extract persistent A frags ----
    half* Qst = (half*)sraw;
    uint32_t Ahi[4][4], Alo[4][4];
    #pragma unroll
    for (int pass = 0; pass < 2; pass++) {
        const half* src = pass ? Qlb : Qhb;
        __syncthreads();
        #pragma unroll
        for (int i = 0; i < 4; i++) {
            int idx = t + i * 256;
            int row = idx >> 3, k8 = (idx & 7) << 3;
            *(uint4*)&Qst[row * 72 + k8] =
                *(const uint4*)(src + (size_t)row * 64 + k8);
        }
        __syncthreads();
        #pragma unroll
        for (int ks = 0; ks < 4; ks++)
            #pragma unroll
            for (int i = 0; i < 4; i++) {
                const int row = 16 * w + r + ((i & 1) << 3);
                const int col = ks * 16 + 2 * c + ((i >> 1) << 3);
                uint32_t v = *(const uint32_t*)&Qst[row * 72 + col];
                if (pass) Alo[ks][i] = v; else Ahi[ks][i] = v;
            }
    }
    __syncthreads();                  // Q extraction done before first scatter

    const int qA = q0 + 16 * w + r, qB = qA + 8;
    float mA = -CUDART_INF_F, lA = 0.f, mB = -CUDART_INF_F, lB = 0.f;

    // prefetch K chunk 0 into regs
    uint4 vh[2], vl[2];
    {
        #pragma unroll
        for (int i = 0; i < 2; i++) {
            int idx = t + i * 256;
            int n = idx >> 3, k8 = (idx & 7) << 3;
            const size_t ofs = (size_t)n * 64 + k8;
            vh[i] = *(const uint4*)(Khb + ofs);
            vl[i] = *(const uint4*)(Klb + ofs);
        }
    }

    for (int kc = 0; kc < NCHUNK; kc++) {
        // scatter current chunk into buf[kc&1]
        uint32_t* Fw = (uint32_t*)sraw[kc & 1];
        #pragma unroll
        for (int i = 0; i < 2; i++) {
            int idx = t + i * 256;
            int n = idx >> 3, k8 = (idx & 7) << 3;
            scat_b(Fw, n, k8, vh[i], 0);
            scat_b(Fw, n, k8, vl[i], 2);
        }
        // prefetch next chunk (latency overlaps barrier + compute)
        if (kc < NCHUNK - 1) {
            #pragma unroll
            for (int i = 0; i < 2; i++) {
                int idx = t + i * 256;
                int n = idx >> 3, k8 = (idx & 7) << 3;
                const size_t ofs = (size_t)((kc + 1) * 64 + n) * 64 + k8;
                vh[i] = *(const uint4*)(Khb + ofs);
                vl[i] = *(const uint4*)(Klb + ofs);
            }
        }
        __syncthreads();              // the ONLY barrier per chunk

        // ---- MMAs for all 8 nt tiles, collect sv + chunk max ----
        const uint4* Fb = (const uint4*)sraw[kc & 1];
        const int kt = kc * 64;
        float sv[8][4];
        float cmA = -CUDART_INF_F, cmB = -CUDART_INF_F;
        #pragma unroll
        for (int nt = 0; nt < 8; nt++) {
            float d[4] = {};
            #pragma unroll
            for (int ks = 0; ks < 4; ks++) {
                uint4 bq = Fb[(nt * 4 + ks) * 33 + lane];
                mma16(d, Ahi[ks], bq.x, bq.y);
                mma16(d, Ahi[ks], bq.z, bq.w);
                mma16(d, Alo[ks], bq.x, bq.y);
            }
            const int col = kt + nt * 8 + 2 * c;
            const float2 mk0 = *(const float2*)(mask + (size_t)qA * S + col);
            const float2 mk1 = *(const float2*)(mask + (size_t)qB * S + col);
            sv[nt][0] = fmaf(d[0], SCALE, mk0.x);
            sv[nt][1] = fmaf(d[1], SCALE, mk0.y);
            sv[nt][2] = fmaf(d[2], SCALE, mk1.x);
            sv[nt][3] = fmaf(d[3], SCALE, mk1.y);
            cmA = fmaxf(cmA, fmaxf(sv[nt][0], sv[nt][1]));
            cmB = fmaxf(cmB, fmaxf(sv[nt][2], sv[nt][3]));
        }
        // quad-wide chunk max (lanes c=0..3 share each row)
        cmA = fmaxf(cmA, __shfl_xor_sync(0xffffffffu, cmA, 1));
        cmA = fmaxf(cmA, __shfl_xor_sync(0xffffffffu, cmA, 2));
        cmB = fmaxf(cmB, __shfl_xor_sync(0xffffffffu, cmB, 1));
        cmB = fmaxf(cmB, __shfl_xor_sync(0xffffffffu, cmB, 2));
        const float mnA = fmaxf(mA, cmA), mnB = fmaxf(mB, cmB);
        lA *= __expf(mA - mnA);
        lB *= __expf(mB - mnB);

        float sA = 0.f, sB = 0.f;
        #pragma unroll
        for (int nt = 0; nt < 8; nt++) {
            const int col = kt + nt * 8 + 2 * c;
            const float e0 = __expf(sv[nt][0] - mnA);
            const float e1 = __expf(sv[nt][1] - mnA);
            const float e2 = __expf(sv[nt][2] - mnB);
            const float e3 = __expf(sv[nt][3] - mnB);
            sA += e0 + e1;
            sB += e2 + e3;
            float2 eA = {e0, e1}, eB = {e2, e3};
            *(float2*)(Ep + (size_t)qA * S + col) = eA;
            *(float2*)(Ep + (size_t)qB * S + col) = eB;
        }
        lA += sA; lB += sB;
        mA = mnA; mB = mnB;
        if (c == 0) {
            g_Mc[(bh * S + qA) * NCHUNK + kc] = mnA;
            g_Mc[(bh * S + qB) * NCHUNK + kc] = mnB;
        }
    }

    // quad merge of l (m already common across quad)
    lA += __shfl_xor_sync(0xffffffffu, lA, 1);
    lA += __shfl_xor_sync(0xffffffffu, lA, 2);
    lB += __shfl_xor_sync(0xffffffffu, lB, 1);
    lB += __shfl_xor_sync(0xffffffffu, lB, 2);
    if (c == 0) {
        g_M[bh * S + qA] = mA; g_Li[bh * S + qA] = 1.f / lA;
        g_M[bh * S + qB] = mB; g_Li[bh * S + qB] = 1.f / lB;
    }
}

// ============================================================
// ctx = P @ V : P = e * CF (no exp), V^T permuted B-frags,
// double-buffered. 256 thr, q-strip 128. grid (16, 32)
// ============================================================
__global__ __launch_bounds__(256) void ctx_mma_kernel()
{
    __shared__ uint4 FragB[2][8 * 4 * 33];

    const int t = threadIdx.x, w = t >> 5, lane = t & 31;
    const int r = lane >> 2, c = lane & 3;
    const int bh = blockIdx.y, q0 = blockIdx.x * 128;
    const int b = bh >> 3, h = bh & 7;
    const float* Ep = g_E + (size_t)bh * S * S;
    const half* Vhb = g_Vth + (size_t)bh * DK * S;
    const half* Vlb = g_Vtl + (size_t)bh * DK * S;

    const int qA = q0 + 16 * w + r, qB = qA + 8;
    const float* cfA_p = g_CF + (bh * S + qA) * NCHUNK;
    const float* cfB_p = g_CF + (bh * S + qB) * NCHUNK;

    float acc[8][4] = {};

    uint4 vh[2], vl[2];
    #pragma unroll
    for (int i = 0; i < 2; i++) {
        int idx = t + i * 256;
        int n = idx >> 3, k8 = (idx & 7) << 3;
        const size_t ofs = (size_t)n * S + k8;
        vh[i] = *(const uint4*)(Vhb + ofs);
        vl[i] = *(const uint4*)(Vlb + ofs);
    }

    for (int kc = 0; kc < NCHUNK; kc++) {
        uint32_t* Fw = (uint32_t*)FragB[kc & 1];
        #pragma unroll
        for (int i = 0; i < 2; i++) {
            int idx = t + i * 256;
            int n = idx >> 3, k8 = (idx & 7) << 3;
            scat_b(Fw, n, k8, vh[i], 0);
            scat_b(Fw, n, k8, vl[i], 2);
        }
        if (kc < NCHUNK - 1) {
            #pragma unroll
            for (int i = 0; i < 2; i++) {
                int idx = t + i * 256;
                int n = idx >> 3, k8 = (idx & 7) << 3;
                const size_t ofs = (size_t)n * S + (kc + 1) * 64 + k8;
                vh[i] = *(const uint4*)(Vhb + ofs);
                vl[i] = *(const uint4*)(Vlb + ofs);
            }
        }
        __syncthreads();

        const uint4* Fb = FragB[kc & 1];
        const int kt = kc * 64;
        const float cfA = cfA_p[kc], cfB = cfB_p[kc];
        #pragma unroll
        for (int ks = 0; ks < 4; ks++) {
            const int k0 = kt + ks * 16 + 2 * c;
            const float2 eA0 = *(const float2*)(Ep + (size_t)qA * S + k0);
            const float2 eB0 = *(const float2*)(Ep + (size_t)qB * S + k0);
            const float2 eA1 = *(const float2*)(Ep + (size_t)qA * S + k0 + 8);
            const float2 eB1 = *(const float2*)(Ep + (size_t)qB * S + k0 + 8);
            uint32_t Ph[4], Pl[4];
            split2(eA0.x * cfA, eA0.y * cfA, Ph[0], Pl[0]);
            split2(eB0.x * cfB, eB0.y * cfB, Ph[1], Pl[1]);
            split2(eA1.x * cfA, eA1.y * cfA, Ph[2], Pl[2]);
            split2(eB1.x * cfB, eB1.y * cfB, Ph[3], Pl[3]);
            #pragma unroll
            for (int nt = 0; nt < 8; nt++) {
                uint4 bq = Fb[(nt * 4 + ks) * 33 + lane];
                mma16(acc[nt], Ph, bq.x, bq.y);
                mma16(acc[nt], Ph, bq.z, bq.w);
                mma16(acc[nt], Pl, bq.x, bq.y);
            }
        }
        // NOTE: no trailing barrier — double buffer + next iteration's
        // barrier orders compute(kc) before scatter(kc+2).
    }

    #pragma unroll
    for (int nt = 0; nt < 8; nt++) {
        const int col = h * 64 + nt * 8 + 2 * c;
        #pragma unroll
        for (int hm = 0; hm < 2; hm++) {
            const int q = hm ? qB : qA;
            uint32_t hi, lo;
            split2(acc[nt][2 * hm], acc[nt][2 * hm + 1], hi, lo);
            const size_t ofs = ((size_t)b * S + q) * 512 + col;
            *(uint32_t*)(g_Ch + ofs) = hi;
            *(uint32_t*)(g_Cl + ofs) = lo;
        }
    }
}

// ============================================================
// attn.mean over heads: p = e * CF, no exp -> pure DRAM.
// ============================================================
__global__ __launch_bounds__(256) void mean_kernel(float* __restrict__ mean)
{
    const size_t i4 = (size_t)blockIdx.x * 256 + threadIdx.x;   // < B*S*S/4
    const size_t per_b = (size_t)S * S / 4;
    const int bb = (int)(i4 / per_b);
    const size_t r4 = i4 - (size_t)bb * per_b;
    const int q  = (int)(r4 / (S / 4));
    const int k  = (int)(r4 % (S / 4)) * 4;
    const int kc = k >> 6;

    float4 acc = {0.f, 0.f, 0.f, 0.f};
    #pragma unroll
    for (int hh = 0; hh < H; hh++) {
        const int row = (bb * H + hh) * S + q;
        const float cf = __ldg(&g_CF[row * NCHUNK + kc]);
        const float4 e = *(const float4*)(g_E + (size_t)row * S + k);
        acc.x = fmaf(e.x, cf, acc.x);
        acc.y = fmaf(e.y, cf, acc.y);
        acc.z = fmaf(e.z, cf, acc.z);
        acc.w = fmaf(e.w, cf, acc.w);
    }
    acc.x *= 0.125f; acc.y *= 0.125f; acc.z *= 0.125f; acc.w *= 0.125f;
    ((float4*)mean)[i4] = acc;
}

// ============================================================
// out = Ctx @ Wout : pre-split A and B, permuted B-frags.
// ============================================================
__global__ __launch_bounds__(128) void out_mma_kernel(float* __restrict__ out)
{
    __shared__ __align__(16) half Ast[2][64 * 72];
    __shared__ uint4 FragB[8 * 4 * 33];
    uint32_t* Fw = (uint32_t*)FragB;

    const int t = threadIdx.x, w = t >> 5, lane = t & 31;
    const int r = lane >> 2, c = lane & 3;
    const int m0 = blockIdx.x * 64;
    const int n0 = blockIdx.y * 64;

    float acc[8][4] = {};

    for (int kt = 0; kt < 512; kt += 64) {
        __syncthreads();
        #pragma unroll
        for (int i = 0; i < 4; i++) {
            int idx = t + i * 128;
            int row = idx >> 3, k8 = (idx & 7) << 3;
            *(uint4*)&Ast[0][row * 72 + k8] =
                *(const uint4*)(g_Ch + (size_t)(m0 + row) * 512 + kt + k8);
            *(uint4*)&Ast[1][row * 72 + k8] =
                *(const uint4*)(g_Cl + (size_t)(m0 + row) * 512 + kt + k8);
        }
        #pragma unroll
        for (int i = 0; i < 4; i++) {
            int idx = t + i * 128;
            int n = idx >> 3, k8 = (idx & 7) << 3;
            uint4 vh = *(const uint4*)(g_WoTh + (size_t)(n0 + n) * 512 + kt + k8);
            uint4 vl = *(const uint4*)(g_WoTl + (size_t)(n0 + n) * 512 + kt + k8);
            scat_b(Fw, n, k8, vh, 0);
            scat_b(Fw, n, k8, vl, 2);
        }
        __syncthreads();

        #pragma unroll
        for (int ks = 0; ks < 4; ks++) {
            uint32_t ahi[4], alo[4];
            #pragma unroll
            for (int i = 0; i < 4; i++) {
                const int row = 16 * w + r + ((i & 1) << 3);
                const int col = ks * 16 + 2 * c + ((i >> 1) << 3);
                ahi[i] = *(const uint32_t*)&Ast[0][row * 72 + col];
                alo[i] = *(const uint32_t*)&Ast[1][row * 72 + col];
            }
            #pragma unroll
            for (int nt = 0; nt < 8; nt++) {
                uint4 bq = FragB[(nt * 4 + ks) * 33 + lane];
                mma16(acc[nt], ahi, bq.x, bq.y);
                mma16(acc[nt], ahi, bq.z, bq.w);
                mma16(acc[nt], alo, bq.x, bq.y);
            }
        }
    }

    const int mA = m0 + 16 * w + r, mB = mA + 8;
    #pragma unroll
    for (int nt = 0; nt < 8; nt++) {
        const int col = n0 + nt * 8 + 2 * c;
        float2 oA = {acc[nt][0], acc[nt][1]};
        float2 oB = {acc[nt][2], acc[nt][3]};
        *(float2*)(out + (size_t)mA * 512 + col) = oA;
        *(float2*)(out + (size_t)mB * 512 + col) = oB;
    }
}

// ============================================================
extern "C" void kernel_launch(void* const* d_in, const int* in_sizes, int n_in,
                              void* d_out, int out_size)
{
    const float* Zq   = (const float*)d_in[0];
    const float* Zkv  = (const float*)d_in[1];
    const float* mask = (const float*)d_in[2];
    const float* Wqkv = (const float*)d_in[3];
    const float* Wout = (const float*)d_in[4];

    float* out  = (float*)d_out;                 // [B,S,D]
    float* mean = out + (size_t)B * S * D;       // [B,S,S]

    half *zqh, *zql, *zkh, *zkl, *wqh, *wql, *woh, *wol;
    cudaGetSymbolAddress((void**)&zqh, g_Zqh);
    cudaGetSymbolAddress((void**)&zql, g_Zql);
    cudaGetSymbolAddress((void**)&zkh, g_Zkh);
    cudaGetSymbolAddress((void**)&zkl, g_Zkl);
    cudaGetSymbolAddress((void**)&wqh, g_WqTh);
    cudaGetSymbolAddress((void**)&wql, g_WqTl);
    cudaGetSymbolAddress((void**)&woh, g_WoTh);
    cudaGetSymbolAddress((void**)&wol, g_WoTl);

    const int nZ4 = B * S * D / 4;
    split_kernel<<<nZ4 / 256, 256>>>((const float4*)Zq,  (uint2*)zqh, (uint2*)zql, nZ4);
    split_kernel<<<nZ4 / 256, 256>>>((const float4*)Zkv, (uint2*)zkh, (uint2*)zkl, nZ4);
    tsplit_kernel<<<(D / 8 * 3 * D) / 256, 256>>>(Wqkv, wqh, wql, D, 3 * D);
    tsplit_kernel<<<(D / 8 * D) / 256, 256>>>(Wout, woh, wol, D, D);

    qkv_mma_kernel<<<dim3(128, 24), 128>>>();
    scores_mma_kernel<<<dim3(16, 32), 256>>>(mask);
    cf_kernel<<<(BH * S * NCHUNK) / 256, 256>>>();
    ctx_mma_kernel<<<dim3(16, 32), 256>>>();
    mean_kernel<<<(B * (size_t)S * S / 4) / 256, 256>>>(mean);
    out_mma_kernel<<<dim3(128, 8), 128>>>(out);
}